// round 9
// baseline (speedup 1.0000x reference)
#include <cuda_runtime.h>
#include <cuda_bf16.h>
#include <cstdint>
#include <math.h>

// Problem constants
#define NT 1024
#define NA 2
#define NE 8
#define NI 2816
#define ND 1024
#define NSLOT (NT * NA)

// GEMM tiling: block 128x128x64, 512 threads (16 warps: 4M x 4N), 2-stage pipe
#define BM 128
#define BN 128
#define BK 64
#define LDS_STRIDE 144             // bytes per smem row (64 bf16 = 128B, +16B pad)
#define TB (128 * LDS_STRIDE)      // one tile: 128 rows x 144B = 18432 B

// ---------------------------------------------------------------------------
// Device global scratch
// ---------------------------------------------------------------------------
__device__ int g_count[NE];
__device__ int g_slots[NE][NSLOT];
__device__ int g_is64;

__device__ __align__(16) __nv_bfloat16 g_xh[NT * ND];
__device__ __align__(16) __nv_bfloat16 g_xl[NT * ND];
__device__ __align__(16) __nv_bfloat16 g_hh[(size_t)NSLOT * NI];
__device__ __align__(16) __nv_bfloat16 g_hl[(size_t)NSLOT * NI];

// ---------------------------------------------------------------------------
// PTX helpers (base-target sm_103 features only)
// ---------------------------------------------------------------------------
__device__ __forceinline__ uint32_t smem_u32(const void* p) {
    uint32_t a;
    asm("{ .reg .u64 t; cvta.to.shared.u64 t, %1; cvt.u32.u64 %0, t; }"
        : "=r"(a) : "l"(p));
    return a;
}

#define LDSM4(R, addr) \
    asm volatile("ldmatrix.sync.aligned.m8n8.x4.shared.b16 {%0,%1,%2,%3}, [%4];" \
        : "=r"((R)[0]), "=r"((R)[1]), "=r"((R)[2]), "=r"((R)[3]) : "r"(addr))

#define MMA_BF16(C, A, B0, B1) \
    asm volatile("mma.sync.aligned.m16n8k16.row.col.f32.bf16.bf16.f32 " \
        "{%0,%1,%2,%3}, {%4,%5,%6,%7}, {%8,%9}, {%0,%1,%2,%3};" \
        : "+f"((C)[0]), "+f"((C)[1]), "+f"((C)[2]), "+f"((C)[3]) \
        : "r"((A)[0]), "r"((A)[1]), "r"((A)[2]), "r"((A)[3]), "r"(B0), "r"(B1))

#define CP_ASYNC16(dst, src) \
    asm volatile("cp.async.cg.shared.global [%0], [%1], 16;" :: "r"(dst), "l"(src))
#define CP_COMMIT() asm volatile("cp.async.commit_group;" ::: "memory")
#define CP_WAIT(N) asm volatile("cp.async.wait_group %0;" :: "n"(N) : "memory")

__device__ __forceinline__ uint16_t bfbits(__nv_bfloat16 b) {
    return *reinterpret_cast<uint16_t*>(&b);
}
__device__ __forceinline__ void split2(float f, uint16_t& h, uint16_t& l) {
    __nv_bfloat16 bh = __float2bfloat16(f);
    __nv_bfloat16 bl = __float2bfloat16(f - __bfloat162float(bh));
    h = bfbits(bh);
    l = bfbits(bl);
}
__device__ __forceinline__ void split8(const float4& a, const float4& b,
                                       uint4& hw, uint4& lw) {
    uint16_t h0, h1, l0, l1;
    split2(a.x, h0, l0); split2(a.y, h1, l1);
    hw.x = (uint32_t)h0 | ((uint32_t)h1 << 16);
    lw.x = (uint32_t)l0 | ((uint32_t)l1 << 16);
    split2(a.z, h0, l0); split2(a.w, h1, l1);
    hw.y = (uint32_t)h0 | ((uint32_t)h1 << 16);
    lw.y = (uint32_t)l0 | ((uint32_t)l1 << 16);
    split2(b.x, h0, l0); split2(b.y, h1, l1);
    hw.z = (uint32_t)h0 | ((uint32_t)h1 << 16);
    lw.z = (uint32_t)l0 | ((uint32_t)l1 << 16);
    split2(b.z, h0, l0); split2(b.w, h1, l1);
    hw.w = (uint32_t)h0 | ((uint32_t)h1 << 16);
    lw.w = (uint32_t)l0 | ((uint32_t)l1 << 16);
}

// ---------------------------------------------------------------------------
// Routing
// ---------------------------------------------------------------------------
__global__ void detect_and_zero_kernel(const int* __restrict__ idx32) {
    __shared__ int any;
    if (threadIdx.x == 0) any = 0;
    if (threadIdx.x < NE) g_count[threadIdx.x] = 0;
    __syncthreads();
    int local = 0;
    for (int i = threadIdx.x; i < NSLOT / 2; i += blockDim.x)
        local |= idx32[2 * i + 1];
    if (local) atomicOr(&any, 1);
    __syncthreads();
    if (threadIdx.x == 0) g_is64 = (any == 0) ? 1 : 0;
}

__global__ void route_kernel(const int* __restrict__ idx32) {
    int s = blockIdx.x * blockDim.x + threadIdx.x;
    if (s < NSLOT) {
        int e = g_is64 ? idx32[2 * s] : idx32[s];
        e &= (NE - 1);
        int p = atomicAdd(&g_count[e], 1);
        g_slots[e][p] = s;
    }
}

// ---------------------------------------------------------------------------
// x: fp32 -> bf16 (hi, lo) split (tiny)
// ---------------------------------------------------------------------------
__global__ __launch_bounds__(256) void split_bf16_kernel(
    const float* __restrict__ src,
    __nv_bfloat16* __restrict__ hi,
    __nv_bfloat16* __restrict__ lo, int n4)
{
    int i = blockIdx.x * blockDim.x + threadIdx.x;
    if (i >= n4) return;
    float4 v = reinterpret_cast<const float4*>(src)[i];
    uint16_t h0, h1, h2, h3, l0, l1, l2, l3;
    split2(v.x, h0, l0); split2(v.y, h1, l1);
    split2(v.z, h2, l2); split2(v.w, h3, l3);
    uint2 hw, lw;
    hw.x = (uint32_t)h0 | ((uint32_t)h1 << 16);
    hw.y = (uint32_t)h2 | ((uint32_t)h3 << 16);
    lw.x = (uint32_t)l0 | ((uint32_t)l1 << 16);
    lw.y = (uint32_t)l2 | ((uint32_t)l3 << 16);
    reinterpret_cast<uint2*>(hi)[i] = hw;
    reinterpret_cast<uint2*>(lo)[i] = lw;
}

// ---------------------------------------------------------------------------
// GEMM1: h = silu(X @ w1[e]^T) * (X @ w3[e]^T)
// BK=64, 2-stage pipeline, ONE barrier per chunk:
//   CP_WAIT(0) -> sync -> cp.async(c+1) -> [W ldg b0 | kb0,1 MMA | W sts b0,
//   W ldg b1 | kb2,3 MMA | W sts b1]
// Stage tiles: Ah, Al, B1h, B1l, B3h, B3l (each 128 x 64 bf16, 144B stride)
// ---------------------------------------------------------------------------
#define STAGE1B (6 * TB)                    // 110592
#define SMEM1_BYTES (1024 + 2 * STAGE1B)    // 222208

__global__ __launch_bounds__(512, 1) void gemm1_tc(
    const float* __restrict__ w1, const float* __restrict__ w3)
{
    const int e = blockIdx.z;
    const int ne = g_count[e];
    const int mBase = blockIdx.y * BM;
    if (mBase >= ne) return;
    const int nBase = blockIdx.x * BN;

    extern __shared__ char smem[];
    const uint32_t sb = smem_u32(smem);
    const int tid = threadIdx.x;
    const int wid = tid >> 5;
    const int lane = tid & 31;

    int* sSlot = reinterpret_cast<int*>(smem);
    if (tid < BM) {
        int m = mBase + tid;
        sSlot[tid] = (m < ne) ? g_slots[e][m] : -1;
    }
    __syncthreads();

    // --- A producer: tile (hi/lo) x row x 64B half; 4 granules of 16B ---
    const int atile = tid >> 8;          // 0: hi, 1: lo
    const int at    = tid & 255;
    const int arow  = at >> 1;
    const int ahalf = at & 1;            // 32 elements each
    const uint32_t adoff = 1024u + (uint32_t)atile * TB
                         + (uint32_t)arow * LDS_STRIDE + ahalf * 64;
    const __nv_bfloat16* asrcp;
    {
        int s = sSlot[arow];
        int tok = (s >= 0 ? s : 0) >> 1;
        asrcp = (atile ? g_xl : g_xh) + (size_t)tok * ND + ahalf * 32;
    }

    // --- W producer: tile (w1/w3) x row x 32-float half; 2 batches of 16 ---
    const int wt    = tid >> 8;
    const int wrow  = (tid & 255) >> 1;
    const int whalf = tid & 1;
    const float* wsrc = (wt == 0 ? w1 : w3)
        + (size_t)e * NI * ND + (size_t)(nBase + wrow) * ND + whalf * 32;
    const uint32_t wdoff = (uint32_t)wrow * LDS_STRIDE + whalf * 64;
    const uint32_t wtoff_h = (uint32_t)(2 + wt * 2) * TB;
    const uint32_t wtoff_l = wtoff_h + TB;

    // --- consumer: 16 warps = 4M x 4N, warp tile 32x32 ---
    const int warpM = wid & 3;
    const int warpN = wid >> 2;
    const uint32_t aoff = (uint32_t)(warpM * 32 + (lane & 15)) * LDS_STRIDE
                        + (uint32_t)(lane >> 4) * 16;
    const uint32_t boff = (uint32_t)(warpN * 32 + (lane & 7) + ((lane >> 3) & 2) * 4) * LDS_STRIDE
                        + (uint32_t)((lane >> 3) & 1) * 16;

    float acc1[2][4][4] = {};
    float acc3[2][4][4] = {};

    const int NCH = ND / BK;   // 16

    // W convert+store helper (16 floats -> 32B hi + 32B lo)
    auto wstore = [&](const float4& s0, const float4& s1, const float4& s2,
                      const float4& s3, uint32_t stg, int b) {
        uint4 hw, lw;
        split8(s0, s1, hw, lw);
        *reinterpret_cast<uint4*>(smem + 1024u + stg + wtoff_h + wdoff + b * 32) = hw;
        *reinterpret_cast<uint4*>(smem + 1024u + stg + wtoff_l + wdoff + b * 32) = lw;
        split8(s2, s3, hw, lw);
        *reinterpret_cast<uint4*>(smem + 1024u + stg + wtoff_h + wdoff + b * 32 + 16) = hw;
        *reinterpret_cast<uint4*>(smem + 1024u + stg + wtoff_l + wdoff + b * 32 + 16) = lw;
    };

    // --- prologue: cp A(0) into stage 0; W(0) both batches into stage 0 ---
    #pragma unroll
    for (int q = 0; q < 4; q++)
        CP_ASYNC16(adoff + sb + q * 16, asrcp + q * 8);
    CP_COMMIT();
    {
        float4 s0 = *reinterpret_cast<const float4*>(wsrc + 0);
        float4 s1 = *reinterpret_cast<const float4*>(wsrc + 4);
        float4 s2 = *reinterpret_cast<const float4*>(wsrc + 8);
        float4 s3 = *reinterpret_cast<const float4*>(wsrc + 12);
        wstore(s0, s1, s2, s3, 0, 0);
        s0 = *reinterpret_cast<const float4*>(wsrc + 16);
        s1 = *reinterpret_cast<const float4*>(wsrc + 20);
        s2 = *reinterpret_cast<const float4*>(wsrc + 24);
        s3 = *reinterpret_cast<const float4*>(wsrc + 28);
        wstore(s0, s1, s2, s3, 0, 1);
    }

    for (int c = 0; c < NCH; c++) {
        const bool haveNext = (c + 1 < NCH);
        const uint32_t stgRd = (uint32_t)(c & 1) * STAGE1B;
        const uint32_t stgWr = (uint32_t)((c + 1) & 1) * STAGE1B;

        // 1. wait for chunk c's A data (the only outstanding group)
        CP_WAIT(0);
        // 2. single barrier: publishes cp data + prior W stores; protects the
        //    write stage (last read at iter c-1) against this iter's writes.
        __syncthreads();
        // 3. prefetch A(c+1)
        if (haveNext) {
            const int kt = (c + 1) * BK;
            #pragma unroll
            for (int q = 0; q < 4; q++)
                CP_ASYNC16(adoff + sb + stgWr + q * 16, asrcp + kt + q * 8);
            CP_COMMIT();
        }

        const uint32_t bb = sb + 1024u + stgRd;
        const uint32_t tAh = bb, tAl = bb + TB;
        const uint32_t tB1h = bb + 2 * TB, tB1l = bb + 3 * TB;
        const uint32_t tB3h = bb + 4 * TB, tB3l = bb + 5 * TB;

        auto do_kb = [&](uint32_t ko) {
            uint32_t ah[2][4], al[2][4];
            #pragma unroll
            for (int mb = 0; mb < 2; mb++) {
                LDSM4(ah[mb], tAh + aoff + mb * (16 * LDS_STRIDE) + ko);
                LDSM4(al[mb], tAl + aoff + mb * (16 * LDS_STRIDE) + ko);
            }
            #pragma unroll
            for (int nb2 = 0; nb2 < 2; nb2++) {
                const uint32_t no = nb2 * (16 * LDS_STRIDE);
                const int j0 = 2 * nb2, j1 = 2 * nb2 + 1;
                uint32_t b1h[4], b3h[4], b1l[4], b3l[4];
                LDSM4(b1h, tB1h + boff + no + ko);
                LDSM4(b3h, tB3h + boff + no + ko);
                MMA_BF16(acc1[0][j0], ah[0], b1h[0], b1h[1]);
                MMA_BF16(acc1[0][j1], ah[0], b1h[2], b1h[3]);
                MMA_BF16(acc1[1][j0], ah[1], b1h[0], b1h[1]);
                MMA_BF16(acc1[1][j1], ah[1], b1h[2], b1h[3]);
                MMA_BF16(acc3[0][j0], ah[0], b3h[0], b3h[1]);
                MMA_BF16(acc3[0][j1], ah[0], b3h[2], b3h[3]);
                MMA_BF16(acc3[1][j0], ah[1], b3h[0], b3h[1]);
                MMA_BF16(acc3[1][j1], ah[1], b3h[2], b3h[3]);
                LDSM4(b1l, tB1l + boff + no + ko);
                LDSM4(b3l, tB3l + boff + no + ko);
                MMA_BF16(acc1[0][j0], al[0], b1h[0], b1h[1]);
                MMA_BF16(acc1[0][j1], al[0], b1h[2], b1h[3]);
                MMA_BF16(acc1[1][j0], al[1], b1h[0], b1h[1]);
                MMA_BF16(acc1[1][j1], al[1], b1h[2], b1h[3]);
                MMA_BF16(acc3[0][j0], al[0], b3h[0], b3h[1]);
                MMA_BF16(acc3[0][j1], al[0], b3h[2], b3h[3]);
                MMA_BF16(acc3[1][j0], al[1], b3h[0], b3h[1]);
                MMA_BF16(acc3[1][j1], al[1], b3h[2], b3h[3]);
                MMA_BF16(acc1[0][j0], ah[0], b1l[0], b1l[1]);
                MMA_BF16(acc1[0][j1], ah[0], b1l[2], b1l[3]);
                MMA_BF16(acc1[1][j0], ah[1], b1l[0], b1l[1]);
                MMA_BF16(acc1[1][j1], ah[1], b1l[2], b1l[3]);
                MMA_BF16(acc3[0][j0], ah[0], b3l[0], b3l[1]);
                MMA_BF16(acc3[0][j1], ah[0], b3l[2], b3l[3]);
                MMA_BF16(acc3[1][j0], ah[1], b3l[0], b3l[1]);
                MMA_BF16(acc3[1][j1], ah[1], b3l[2], b3l[3]);
            }
        };

        // 4a. stage W(c+1) batch0
        float4 s0, s1, s2, s3;
        if (haveNext) {
            const int kt = (c + 1) * BK;
            s0 = *reinterpret_cast<const float4*>(wsrc + kt + 0);
            s1 = *reinterpret_cast<const float4*>(wsrc + kt + 4);
            s2 = *reinterpret_cast<const float4*>(wsrc + kt + 8);
            s3 = *reinterpret_cast<const float4*>(wsrc + kt + 12);
        }
        do_kb(0);
        do_kb(32);
        if (haveNext) {
            const int kt = (c + 1) * BK;
            wstore(s0, s1, s2, s3, stgWr, 0);
            s0 = *reinterpret_cast<const float4*>(wsrc + kt + 16);
            s1 = *reinterpret_cast<const float4*>(wsrc + kt + 20);
            s2 = *reinterpret_cast<const float4*>(wsrc + kt + 24);
            s3 = *reinterpret_cast<const float4*>(wsrc + kt + 28);
        }
        do_kb(64);
        do_kb(96);
        if (haveNext) wstore(s0, s1, s2, s3, stgWr, 1);
    }

    // --- epilogue: SwiGLU, split to bf16 hi/lo, direct stores ---
    const int g = lane >> 2;
    const int tg = lane & 3;
    #pragma unroll
    for (int mb = 0; mb < 2; mb++) {
        #pragma unroll
        for (int half = 0; half < 2; half++) {
            const int r = warpM * 32 + mb * 16 + g + half * 8;
            const int s = sSlot[r];
            if (s < 0) continue;
            #pragma unroll
            for (int nb = 0; nb < 4; nb++) {
                const float v1a = acc1[mb][nb][half * 2];
                const float v1b = acc1[mb][nb][half * 2 + 1];
                const float v3a = acc3[mb][nb][half * 2];
                const float v3b = acc3[mb][nb][half * 2 + 1];
                const float ha = v1a / (1.0f + __expf(-v1a)) * v3a;
                const float hb = v1b / (1.0f + __expf(-v1b)) * v3b;
                uint16_t hha, hla, hhb, hlb;
                split2(ha, hha, hla);
                split2(hb, hhb, hlb);
                const size_t o = (size_t)s * NI + (nBase + warpN * 32 + nb * 8 + tg * 2);
                *reinterpret_cast<uint32_t*>(g_hh + o) = (uint32_t)hha | ((uint32_t)hhb << 16);
                *reinterpret_cast<uint32_t*>(g_hl + o) = (uint32_t)hla | ((uint32_t)hlb << 16);
            }
        }
    }
}

// ---------------------------------------------------------------------------
// GEMM2: out[slot,:] = h[slot,:] @ w2[e]^T. BK=64, 2-stage, 1 barrier/chunk.
// Stage tiles: Ah, Al, Bh, Bl
// ---------------------------------------------------------------------------
#define STAGE2B (4 * TB)                    // 73728
#define SMEM2_BYTES (1024 + 2 * STAGE2B)    // 148480

__global__ __launch_bounds__(512, 1) void gemm2_tc(
    const float* __restrict__ w2, float* __restrict__ out)
{
    const int e = blockIdx.z;
    const int ne = g_count[e];
    const int mBase = blockIdx.y * BM;
    if (mBase >= ne) return;
    const int nBase = blockIdx.x * BN;

    extern __shared__ char smem[];
    const uint32_t sb = smem_u32(smem);
    const int tid = threadIdx.x;
    const int wid = tid >> 5;
    const int lane = tid & 31;

    int* sSlot = reinterpret_cast<int*>(smem);
    if (tid < BM) {
        int m = mBase + tid;
        sSlot[tid] = (m < ne) ? g_slots[e][m] : -1;
    }
    __syncthreads();

    // --- A producer ---
    const int atile = tid >> 8;
    const int at    = tid & 255;
    const int arow  = at >> 1;
    const int ahalf = at & 1;
    const uint32_t adoff = 1024u + (uint32_t)atile * TB
                         + (uint32_t)arow * LDS_STRIDE + ahalf * 64;
    const __nv_bfloat16* asrcp;
    {
        int s = sSlot[arow];
        int sl = (s >= 0 ? s : 0);
        asrcp = (atile ? g_hl : g_hh) + (size_t)sl * NI + ahalf * 32;
    }

    // --- W producer: 1 tile, 16 fp32 per thread per chunk ---
    const int wrow = tid >> 2;
    const int wq   = tid & 3;
    const float* wsrc = w2 + (size_t)e * ND * NI + (size_t)(nBase + wrow) * NI + wq * 16;
    const uint32_t wdoff = (uint32_t)wrow * LDS_STRIDE + wq * 32;
    const uint32_t wtoff_h = 2u * TB;
    const uint32_t wtoff_l = 3u * TB;

    const int warpM = wid & 3;
    const int warpN = wid >> 2;
    const uint32_t aoff = (uint32_t)(warpM * 32 + (lane & 15)) * LDS_STRIDE
                        + (uint32_t)(lane >> 4) * 16;
    const uint32_t boff = (uint32_t)(warpN * 32 + (lane & 7) + ((lane >> 3) & 2) * 4) * LDS_STRIDE
                        + (uint32_t)((lane >> 3) & 1) * 16;

    float acc[2][4][4] = {};

    const int NCH = NI / BK;   // 44

    auto wstore = [&](const float4& s0, const float4& s1, const float4& s2,
                      const float4& s3, uint32_t stg) {
        uint4 hw, lw;
        split8(s0, s1, hw, lw);
        *reinterpret_cast<uint4*>(smem + 1024u + stg + wtoff_h + wdoff) = hw;
        *reinterpret_cast<uint4*>(smem + 1024u + stg + wtoff_l + wdoff) = lw;
        split8(s2, s3, hw, lw);
        *reinterpret_cast<uint4*>(smem + 1024u + stg + wtoff_h + wdoff + 16) = hw;
        *reinterpret_cast<uint4*>(smem + 1024u + stg + wtoff_l + wdoff + 16) = lw;
    };

    // --- prologue ---
    #pragma unroll
    for (int q = 0; q < 4; q++)
        CP_ASYNC16(adoff + sb + q * 16, asrcp + q * 8);
    CP_COMMIT();
    {
        float4 s0 = *reinterpret_cast<const float4*>(wsrc + 0);
        float4 s1 = *reinterpret_cast<const float4*>(wsrc + 4);
        float4 s2 = *reinterpret_cast<const float4*>(wsrc + 8);
        float4 s3 = *reinterpret_cast<const float4*>(wsrc + 12);
        wstore(s0, s1, s2, s3, 0);
    }

    for (int c = 0; c < NCH; c++) {
        const bool haveNext = (c + 1 < NCH);
        const uint32_t stgRd = (uint32_t)(c & 1) * STAGE2B;
        const uint32_t stgWr = (uint32_t)((c + 1) & 1) * STAGE2B;

        CP_WAIT(0);
        __syncthreads();
        if (haveNext) {
            const int kt = (c + 1) * BK;
            #pragma unroll
            for (int q = 0; q < 4; q++)
                CP_ASYNC16(adoff + sb + stgWr + q * 16, asrcp + kt + q * 8);
            CP_COMMIT();
        }

        const uint32_t bb = sb + 1024u + stgRd;
        const uint32_t tAh = bb, tAl = bb + TB;
        const uint32_t tBh = bb + 2 * TB, tBl = bb + 3 * TB;

        auto do_kb = [&](uint32_t ko) {
            uint32_t ah[2][4], al[2][4];
            #pragma unroll
            for (int mb = 0; mb < 2; mb++) {
                LDSM4(ah[mb], tAh + aoff + mb * (16 * LDS_STRIDE) + ko);
                LDSM4(al[mb], tAl + aoff + mb * (16 * LDS_STRIDE) + ko);
            }
            uint32_t bh0[4], bh1[4], bl0[4], bl1[4];
            LDSM4(bh0, tBh + boff + ko);
            LDSM4(bh1, tBh + boff + 16 * LDS_STRIDE + ko);
            MMA_BF16(acc[0][0], ah[0], bh0[0], bh0[1]);
            MMA_BF16(acc[0][1], ah[0], bh0[2], bh0[3]);
            MMA_BF16(acc[1][0], ah[1], bh0[0], bh0[1]);
            MMA_BF16(acc[1][1], ah[1], bh0[2], bh0[3]);
            MMA_BF16(acc[0][2], ah[0], bh1[0], bh1[1]);
            MMA_BF16(acc[0][3], ah[0], bh1[2], bh1[3]);
            MMA_BF16(acc[1][2], ah[1], bh1[0], bh1[1]);
            MMA_BF16(acc[1][3], ah[1], bh1[2], bh1[3]);
            LDSM4(bl0, tBl + boff + ko);
            LDSM4(bl1, tBl + boff + 16 * LDS_STRIDE + ko);
            MMA_BF16(acc[0][0], al[0], bh0[0], bh0[1]);
            MMA_BF16(acc[0][1], al[0], bh0[2], bh0[3]);
            MMA_BF16(acc[1][0], al[1], bh0[0], bh0[1]);
            MMA_BF16(acc[1][1], al[1], bh0[2], bh0[3]);
            MMA_BF16(acc[0][2], al[0], bh1[0], bh1[1]);
            MMA_BF16(acc[0][3], al[0], bh1[2], bh1[3]);
            MMA_BF16(acc[1][2], al[1], bh1[0], bh1[1]);
            MMA_BF16(acc[1][3], al[1], bh1[2], bh1[3]);
            MMA_BF16(acc[0][0], ah[0], bl0[0], bl0[1]);
            MMA_BF16(acc[0][1], ah[0], bl0[2], bl0[3]);
            MMA_BF16(acc[1][0], ah[1], bl0[0], bl0[1]);
            MMA_BF16(acc[1][1], ah[1], bl0[2], bl0[3]);
            MMA_BF16(acc[0][2], ah[0], bl1[0], bl1[1]);
            MMA_BF16(acc[0][3], ah[0], bl1[2], bl1[3]);
            MMA_BF16(acc[1][2], ah[1], bl1[0], bl1[1]);
            MMA_BF16(acc[1][3], ah[1], bl1[2], bl1[3]);
        };

        float4 s0, s1, s2, s3;
        if (haveNext) {
            const int kt = (c + 1) * BK;
            s0 = *reinterpret_cast<const float4*>(wsrc + kt + 0);
            s1 = *reinterpret_cast<const float4*>(wsrc + kt + 4);
            s2 = *reinterpret_cast<const float4*>(wsrc + kt + 8);
            s3 = *reinterpret_cast<const float4*>(wsrc + kt + 12);
        }
        do_kb(0);
        do_kb(32);
        do_kb(64);
        do_kb(96);
        if (haveNext) wstore(s0, s1, s2, s3, stgWr);
    }

    // --- epilogue: fp32 direct stores ---
    const int g = lane >> 2;
    const int tg = lane & 3;
    #pragma unroll
    for (int mb = 0; mb < 2; mb++) {
        #pragma unroll
        for (int half = 0; half < 2; half++) {
            const int r = warpM * 32 + mb * 16 + g + half * 8;
            const int s = sSlot[r];
            if (s < 0) continue;
            #pragma unroll
            for (int nb = 0; nb < 4; nb++) {
                float2 v;
                v.x = acc[mb][nb][half * 2];
                v.y = acc[mb][nb][half * 2 + 1];
                const size_t o = (size_t)s * ND + (nBase + warpN * 32 + nb * 8 + tg * 2);
                *reinterpret_cast<float2*>(out + o) = v;
            }
        }
    }
}

// ---------------------------------------------------------------------------
// Launch. Inputs (metadata order): x, w1, w2, w3, expert_indices.
// ---------------------------------------------------------------------------
extern "C" void kernel_launch(void* const* d_in, const int* in_sizes, int n_in,
                              void* d_out, int out_size) {
    const float* x  = (const float*)d_in[0];
    const float* w1 = (const float*)d_in[1];
    const float* w2 = (const float*)d_in[2];
    const float* w3 = (const float*)d_in[3];
    const int*   idx = (const int*)d_in[4];
    float* out = (float*)d_out;

    cudaFuncSetAttribute(gemm1_tc, cudaFuncAttributeMaxDynamicSharedMemorySize, SMEM1_BYTES);
    cudaFuncSetAttribute(gemm2_tc, cudaFuncAttributeMaxDynamicSharedMemorySize, SMEM2_BYTES);

    __nv_bfloat16 *xh, *xl;
    cudaGetSymbolAddress((void**)&xh, g_xh);
    cudaGetSymbolAddress((void**)&xl, g_xl);

    detect_and_zero_kernel<<<1, 256>>>(idx);
    route_kernel<<<NSLOT / 256, 256>>>(idx);

    const int nX4 = NT * ND / 4;
    split_bf16_kernel<<<nX4 / 256, 256>>>(x, xh, xl, nX4);

    gemm1_tc<<<dim3(NI / BN, NSLOT / BM, NE), 512, SMEM1_BYTES>>>(w1, w3);
    gemm2_tc<<<dim3(ND / BN, NSLOT / BM, NE), 512, SMEM2_BYTES>>>(w2, out);
}

// round 10
// speedup vs baseline: 1.8921x; 1.8921x over previous
#include <cuda_runtime.h>
#include <cuda_fp16.h>
#include <cstdint>
#include <math.h>

// Problem constants
#define NT 1024
#define NA 2
#define NE 8
#define NI 2816
#define ND 1024
#define NSLOT (NT * NA)

// GEMM tiling: block 128x128x32, 512 threads (16 warps: 4M x 4N), 3-stage pipe
#define BM 128
#define BN 128
#define BK 32
#define LDS_STRIDE 80              // bytes per smem tile row (32*2 padded to 80)
#define TB (128 * LDS_STRIDE)      // one tile: 128 rows x 80B = 10240 B

// ---------------------------------------------------------------------------
// Device global scratch
// ---------------------------------------------------------------------------
__device__ int g_count[NE];
__device__ int g_slots[NE][NSLOT];
__device__ int g_is64;

__device__ __align__(16) __half g_xh[NT * ND];
__device__ __align__(16) __half g_xl[NT * ND];
__device__ __align__(16) __half g_hh[(size_t)NSLOT * NI];
__device__ __align__(16) __half g_hl[(size_t)NSLOT * NI];

// ---------------------------------------------------------------------------
// PTX helpers (base-target sm_103 features only)
// ---------------------------------------------------------------------------
__device__ __forceinline__ uint32_t smem_u32(const void* p) {
    uint32_t a;
    asm("{ .reg .u64 t; cvta.to.shared.u64 t, %1; cvt.u32.u64 %0, t; }"
        : "=r"(a) : "l"(p));
    return a;
}

#define LDSM4(R, addr) \
    asm volatile("ldmatrix.sync.aligned.m8n8.x4.shared.b16 {%0,%1,%2,%3}, [%4];" \
        : "=r"((R)[0]), "=r"((R)[1]), "=r"((R)[2]), "=r"((R)[3]) : "r"(addr))

#define MMA_F16(C, A, B0, B1) \
    asm volatile("mma.sync.aligned.m16n8k16.row.col.f32.f16.f16.f32 " \
        "{%0,%1,%2,%3}, {%4,%5,%6,%7}, {%8,%9}, {%0,%1,%2,%3};" \
        : "+f"((C)[0]), "+f"((C)[1]), "+f"((C)[2]), "+f"((C)[3]) \
        : "r"((A)[0]), "r"((A)[1]), "r"((A)[2]), "r"((A)[3]), "r"(B0), "r"(B1))

#define CP_ASYNC16(dst, src) \
    asm volatile("cp.async.cg.shared.global [%0], [%1], 16;" :: "r"(dst), "l"(src))
#define CP_COMMIT() asm volatile("cp.async.commit_group;" ::: "memory")
#define CP_WAIT(N) asm volatile("cp.async.wait_group %0;" :: "n"(N) : "memory")

__device__ __forceinline__ uint32_t pack2h(float a, float b) {
    __half2 h = __floats2half2_rn(a, b);
    return *reinterpret_cast<uint32_t*>(&h);
}
// fp16 hi/lo split of one float
__device__ __forceinline__ void split2h(float f, uint16_t& h, uint16_t& l) {
    __half hh = __float2half_rn(f);
    __half ll = __float2half_rn(f - __half2float(hh));
    h = *reinterpret_cast<uint16_t*>(&hh);
    l = *reinterpret_cast<uint16_t*>(&ll);
}
// 8 fp32 -> 8 packed fp16 (uint4)
__device__ __forceinline__ uint4 pack8h(const float4& a, const float4& b) {
    uint4 r;
    r.x = pack2h(a.x, a.y);
    r.y = pack2h(a.z, a.w);
    r.z = pack2h(b.x, b.y);
    r.w = pack2h(b.z, b.w);
    return r;
}

// ---------------------------------------------------------------------------
// Routing
// ---------------------------------------------------------------------------
__global__ void detect_and_zero_kernel(const int* __restrict__ idx32) {
    __shared__ int any;
    if (threadIdx.x == 0) any = 0;
    if (threadIdx.x < NE) g_count[threadIdx.x] = 0;
    __syncthreads();
    int local = 0;
    for (int i = threadIdx.x; i < NSLOT / 2; i += blockDim.x)
        local |= idx32[2 * i + 1];
    if (local) atomicOr(&any, 1);
    __syncthreads();
    if (threadIdx.x == 0) g_is64 = (any == 0) ? 1 : 0;
}

__global__ void route_kernel(const int* __restrict__ idx32) {
    int s = blockIdx.x * blockDim.x + threadIdx.x;
    if (s < NSLOT) {
        int e = g_is64 ? idx32[2 * s] : idx32[s];
        e &= (NE - 1);
        int p = atomicAdd(&g_count[e], 1);
        g_slots[e][p] = s;
    }
}

// ---------------------------------------------------------------------------
// x: fp32 -> fp16 (hi, lo) split (tiny)
// ---------------------------------------------------------------------------
__global__ __launch_bounds__(256) void split_f16_kernel(
    const float* __restrict__ src,
    __half* __restrict__ hi,
    __half* __restrict__ lo, int n4)
{
    int i = blockIdx.x * blockDim.x + threadIdx.x;
    if (i >= n4) return;
    float4 v = reinterpret_cast<const float4*>(src)[i];
    uint16_t h0, h1, h2, h3, l0, l1, l2, l3;
    split2h(v.x, h0, l0); split2h(v.y, h1, l1);
    split2h(v.z, h2, l2); split2h(v.w, h3, l3);
    uint2 hw, lw;
    hw.x = (uint32_t)h0 | ((uint32_t)h1 << 16);
    hw.y = (uint32_t)h2 | ((uint32_t)h3 << 16);
    lw.x = (uint32_t)l0 | ((uint32_t)l1 << 16);
    lw.y = (uint32_t)l2 | ((uint32_t)l3 << 16);
    reinterpret_cast<uint2*>(hi)[i] = hw;
    reinterpret_cast<uint2*>(lo)[i] = lw;
}

// ---------------------------------------------------------------------------
// GEMM1: h = silu(X @ w1[e]^T) * (X @ w3[e]^T)
// x split fp16 hi/lo (2 terms), weights single fp16.
// 3-stage pipeline, ONE barrier per chunk (exact R7 skeleton):
//   CP_WAIT -> __syncthreads -> cp.async(c+2) -> W LDG(c+1) -> MMA(c) -> W STS(c+1)
// Stage tiles: Ah, Al, B1, B3 (each 128 x 32 fp16, 80B stride)
// ---------------------------------------------------------------------------
#define STAGE1B (4 * TB)                    // 40960
#define SMEM1_BYTES (1024 + 3 * STAGE1B)    // 123904

__global__ __launch_bounds__(512, 1) void gemm1_tc(
    const float* __restrict__ w1, const float* __restrict__ w3)
{
    const int e = blockIdx.z;
    const int ne = g_count[e];
    const int mBase = blockIdx.y * BM;
    if (mBase >= ne) return;
    const int nBase = blockIdx.x * BN;

    extern __shared__ char smem[];
    const uint32_t sb = smem_u32(smem);
    const int tid = threadIdx.x;
    const int wid = tid >> 5;
    const int lane = tid & 31;

    int* sSlot = reinterpret_cast<int*>(smem);
    if (tid < BM) {
        int m = mBase + tid;
        sSlot[tid] = (m < ne) ? g_slots[e][m] : -1;
    }
    __syncthreads();

    // --- A producer: one 16B granule per tile (hi, lo) ---
    const int prow = tid >> 2;
    const int pcolg = tid & 3;
    const uint32_t adoff = 1024u + (uint32_t)prow * LDS_STRIDE + pcolg * 16;
    const __half* asrc[2];
    {
        int s = sSlot[prow];
        int tok = (s >= 0 ? s : 0) >> 1;
        asrc[0] = g_xh + (size_t)tok * ND + pcolg * 8;
        asrc[1] = g_xl + (size_t)tok * ND + pcolg * 8;
    }

    // --- W producer: 16 fp32 -> 16 fp16 per thread per chunk (w1 or w3) ---
    const int wt    = tid >> 8;            // 0: w1, 1: w3
    const int wrow  = (tid & 255) >> 1;    // 0..127
    const int whalf = tid & 1;             // 16 floats each
    const float* wsrc = (wt == 0 ? w1 : w3)
        + (size_t)e * NI * ND + (size_t)(nBase + wrow) * ND + whalf * 16;
    const uint32_t wdoff = (uint32_t)wrow * LDS_STRIDE + whalf * 32;
    const uint32_t wtoff = (uint32_t)(2 + wt) * TB;   // B1 or B3 within stage

    // --- consumer: 16 warps = 4M x 4N, warp tile 32x32 ---
    const int warpM = wid & 3;
    const int warpN = wid >> 2;
    const uint32_t aoff = (uint32_t)(warpM * 32 + (lane & 15)) * LDS_STRIDE
                        + (uint32_t)(lane >> 4) * 16;
    const uint32_t boff = (uint32_t)(warpN * 32 + (lane & 7) + ((lane >> 3) & 2) * 4) * LDS_STRIDE
                        + (uint32_t)((lane >> 3) & 1) * 16;

    float acc1[2][4][4] = {};
    float acc3[2][4][4] = {};

    const int NCH = ND / BK;   // 32

    // --- prologue: cp A for chunks 0,1 (stages 0,1); convert+store W chunk 0 ---
    CP_ASYNC16(adoff + sb, asrc[0]);
    CP_ASYNC16(adoff + sb + TB, asrc[1]);
    CP_COMMIT();
    CP_ASYNC16(adoff + sb + STAGE1B, asrc[0] + BK);
    CP_ASYNC16(adoff + sb + STAGE1B + TB, asrc[1] + BK);
    CP_COMMIT();
    {
        float4 s0 = *reinterpret_cast<const float4*>(wsrc + 0);
        float4 s1 = *reinterpret_cast<const float4*>(wsrc + 4);
        float4 s2 = *reinterpret_cast<const float4*>(wsrc + 8);
        float4 s3 = *reinterpret_cast<const float4*>(wsrc + 12);
        *reinterpret_cast<uint4*>(smem + 1024u + wtoff + wdoff)      = pack8h(s0, s1);
        *reinterpret_cast<uint4*>(smem + 1024u + wtoff + wdoff + 16) = pack8h(s2, s3);
    }

    uint32_t stgRd = 0, stgW = STAGE1B, stgCp = 2 * STAGE1B;

    for (int c = 0; c < NCH; c++) {
        const bool haveCp = (c + 2 < NCH);
        const bool haveW  = (c + 1 < NCH);

        if (c + 1 < NCH) { CP_WAIT(1); } else { CP_WAIT(0); }
        __syncthreads();
        if (haveCp) {
            const int kt = (c + 2) * BK;
            CP_ASYNC16(adoff + sb + stgCp, asrc[0] + kt);
            CP_ASYNC16(adoff + sb + stgCp + TB, asrc[1] + kt);
            CP_COMMIT();
        }
        float4 s0, s1, s2, s3;
        if (haveW) {
            const int kt = (c + 1) * BK;
            s0 = *reinterpret_cast<const float4*>(wsrc + kt + 0);
            s1 = *reinterpret_cast<const float4*>(wsrc + kt + 4);
            s2 = *reinterpret_cast<const float4*>(wsrc + kt + 8);
            s3 = *reinterpret_cast<const float4*>(wsrc + kt + 12);
        }

        const uint32_t bb = sb + 1024u + stgRd;
        const uint32_t tAh = bb, tAl = bb + TB;
        const uint32_t tB1 = bb + 2 * TB, tB3 = bb + 3 * TB;

        #pragma unroll
        for (int kb = 0; kb < 2; kb++) {
            const uint32_t ko = kb * 32;
            uint32_t ah[2][4], al[2][4];
            #pragma unroll
            for (int mb = 0; mb < 2; mb++) {
                LDSM4(ah[mb], tAh + aoff + mb * (16 * LDS_STRIDE) + ko);
                LDSM4(al[mb], tAl + aoff + mb * (16 * LDS_STRIDE) + ko);
            }
            #pragma unroll
            for (int nb2 = 0; nb2 < 2; nb2++) {
                const uint32_t no = nb2 * (16 * LDS_STRIDE);
                const int j0 = 2 * nb2, j1 = 2 * nb2 + 1;
                uint32_t b1[4], b3[4];
                LDSM4(b1, tB1 + boff + no + ko);
                LDSM4(b3, tB3 + boff + no + ko);
                // pass1: ah x {b1,b3}  (8 distinct C)
                MMA_F16(acc1[0][j0], ah[0], b1[0], b1[1]);
                MMA_F16(acc1[0][j1], ah[0], b1[2], b1[3]);
                MMA_F16(acc1[1][j0], ah[1], b1[0], b1[1]);
                MMA_F16(acc1[1][j1], ah[1], b1[2], b1[3]);
                MMA_F16(acc3[0][j0], ah[0], b3[0], b3[1]);
                MMA_F16(acc3[0][j1], ah[0], b3[2], b3[3]);
                MMA_F16(acc3[1][j0], ah[1], b3[0], b3[1]);
                MMA_F16(acc3[1][j1], ah[1], b3[2], b3[3]);
                // pass2: al x {b1,b3}
                MMA_F16(acc1[0][j0], al[0], b1[0], b1[1]);
                MMA_F16(acc1[0][j1], al[0], b1[2], b1[3]);
                MMA_F16(acc1[1][j0], al[1], b1[0], b1[1]);
                MMA_F16(acc1[1][j1], al[1], b1[2], b1[3]);
                MMA_F16(acc3[0][j0], al[0], b3[0], b3[1]);
                MMA_F16(acc3[0][j1], al[0], b3[2], b3[3]);
                MMA_F16(acc3[1][j0], al[1], b3[0], b3[1]);
                MMA_F16(acc3[1][j1], al[1], b3[2], b3[3]);
            }
        }

        if (haveW) {
            *reinterpret_cast<uint4*>(smem + 1024u + stgW + wtoff + wdoff)      = pack8h(s0, s1);
            *reinterpret_cast<uint4*>(smem + 1024u + stgW + wtoff + wdoff + 16) = pack8h(s2, s3);
        }
        const uint32_t t = stgRd;
        stgRd = stgW; stgW = stgCp; stgCp = t;
    }

    // --- epilogue: SwiGLU, split to fp16 hi/lo, direct stores ---
    const int g = lane >> 2;
    const int tg = lane & 3;
    #pragma unroll
    for (int mb = 0; mb < 2; mb++) {
        #pragma unroll
        for (int half = 0; half < 2; half++) {
            const int r = warpM * 32 + mb * 16 + g + half * 8;
            const int s = sSlot[r];
            if (s < 0) continue;
            #pragma unroll
            for (int nb = 0; nb < 4; nb++) {
                const float v1a = acc1[mb][nb][half * 2];
                const float v1b = acc1[mb][nb][half * 2 + 1];
                const float v3a = acc3[mb][nb][half * 2];
                const float v3b = acc3[mb][nb][half * 2 + 1];
                const float ha = v1a / (1.0f + __expf(-v1a)) * v3a;
                const float hb = v1b / (1.0f + __expf(-v1b)) * v3b;
                uint16_t hha, hla, hhb, hlb;
                split2h(ha, hha, hla);
                split2h(hb, hhb, hlb);
                const size_t o = (size_t)s * NI + (nBase + warpN * 32 + nb * 8 + tg * 2);
                *reinterpret_cast<uint32_t*>(g_hh + o) = (uint32_t)hha | ((uint32_t)hhb << 16);
                *reinterpret_cast<uint32_t*>(g_hl + o) = (uint32_t)hla | ((uint32_t)hlb << 16);
            }
        }
    }
}

// ---------------------------------------------------------------------------
// GEMM2: out[slot,:] = h[slot,:] @ w2[e]^T. h fp16 hi/lo, w2 single fp16.
// Same 3-stage / 1-barrier scheme. Stage tiles: Ah, Al, B.
// ---------------------------------------------------------------------------
#define STAGE2B (3 * TB)                    // 30720
#define SMEM2_BYTES (1024 + 3 * STAGE2B)    // 93184

__global__ __launch_bounds__(512, 1) void gemm2_tc(
    const float* __restrict__ w2, float* __restrict__ out)
{
    const int e = blockIdx.z;
    const int ne = g_count[e];
    const int mBase = blockIdx.y * BM;
    if (mBase >= ne) return;
    const int nBase = blockIdx.x * BN;

    extern __shared__ char smem[];
    const uint32_t sb = smem_u32(smem);
    const int tid = threadIdx.x;
    const int wid = tid >> 5;
    const int lane = tid & 31;

    int* sSlot = reinterpret_cast<int*>(smem);
    if (tid < BM) {
        int m = mBase + tid;
        sSlot[tid] = (m < ne) ? g_slots[e][m] : -1;
    }
    __syncthreads();

    const int prow = tid >> 2;
    const int pcolg = tid & 3;
    const uint32_t adoff = 1024u + (uint32_t)prow * LDS_STRIDE + pcolg * 16;
    const __half* asrc[2];
    {
        int s = sSlot[prow];
        int sl = (s >= 0 ? s : 0);
        asrc[0] = g_hh + (size_t)sl * NI + pcolg * 8;
        asrc[1] = g_hl + (size_t)sl * NI + pcolg * 8;
    }

    // W producer: 8 fp32 -> 8 fp16 per thread per chunk
    const int wrow = tid >> 2;
    const int wq   = tid & 3;
    const float* wsrc = w2 + (size_t)e * ND * NI + (size_t)(nBase + wrow) * NI + wq * 8;
    const uint32_t wdoff = (uint32_t)wrow * LDS_STRIDE + wq * 16;
    const uint32_t wtoff = 2u * TB;

    const int warpM = wid & 3;
    const int warpN = wid >> 2;
    const uint32_t aoff = (uint32_t)(warpM * 32 + (lane & 15)) * LDS_STRIDE
                        + (uint32_t)(lane >> 4) * 16;
    const uint32_t boff = (uint32_t)(warpN * 32 + (lane & 7) + ((lane >> 3) & 2) * 4) * LDS_STRIDE
                        + (uint32_t)((lane >> 3) & 1) * 16;

    float acc[2][4][4] = {};

    const int NCH = NI / BK;   // 88

    // --- prologue ---
    CP_ASYNC16(adoff + sb, asrc[0]);
    CP_ASYNC16(adoff + sb + TB, asrc[1]);
    CP_COMMIT();
    CP_ASYNC16(adoff + sb + STAGE2B, asrc[0] + BK);
    CP_ASYNC16(adoff + sb + STAGE2B + TB, asrc[1] + BK);
    CP_COMMIT();
    {
        float4 s0 = *reinterpret_cast<const float4*>(wsrc + 0);
        float4 s1 = *reinterpret_cast<const float4*>(wsrc + 4);
        *reinterpret_cast<uint4*>(smem + 1024u + wtoff + wdoff) = pack8h(s0, s1);
    }

    uint32_t stgRd = 0, stgW = STAGE2B, stgCp = 2 * STAGE2B;

    for (int c = 0; c < NCH; c++) {
        const bool haveCp = (c + 2 < NCH);
        const bool haveW  = (c + 1 < NCH);

        if (c + 1 < NCH) { CP_WAIT(1); } else { CP_WAIT(0); }
        __syncthreads();
        if (haveCp) {
            const int kt = (c + 2) * BK;
            CP_ASYNC16(adoff + sb + stgCp, asrc[0] + kt);
            CP_ASYNC16(adoff + sb + stgCp + TB, asrc[1] + kt);
            CP_COMMIT();
        }
        float4 s0, s1;
        if (haveW) {
            const int kt = (c + 1) * BK;
            s0 = *reinterpret_cast<const float4*>(wsrc + kt + 0);
            s1 = *reinterpret_cast<const float4*>(wsrc + kt + 4);
        }

        const uint32_t bb = sb + 1024u + stgRd;
        const uint32_t tAh = bb, tAl = bb + TB;
        const uint32_t tBh = bb + 2 * TB;

        #pragma unroll
        for (int kb = 0; kb < 2; kb++) {
            const uint32_t ko = kb * 32;
            uint32_t ah[2][4], al[2][4];
            #pragma unroll
            for (int mb = 0; mb < 2; mb++) {
                LDSM4(ah[mb], tAh + aoff + mb * (16 * LDS_STRIDE) + ko);
                LDSM4(al[mb], tAl + aoff + mb * (16 * LDS_STRIDE) + ko);
            }
            uint32_t bh0[4], bh1[4];
            LDSM4(bh0, tBh + boff + ko);
            LDSM4(bh1, tBh + boff + 16 * LDS_STRIDE + ko);
            // pass1: ah x bh (8 distinct C)
            MMA_F16(acc[0][0], ah[0], bh0[0], bh0[1]);
            MMA_F16(acc[0][1], ah[0], bh0[2], bh0[3]);
            MMA_F16(acc[1][0], ah[1], bh0[0], bh0[1]);
            MMA_F16(acc[1][1], ah[1], bh0[2], bh0[3]);
            MMA_F16(acc[0][2], ah[0], bh1[0], bh1[1]);
            MMA_F16(acc[0][3], ah[0], bh1[2], bh1[3]);
            MMA_F16(acc[1][2], ah[1], bh1[0], bh1[1]);
            MMA_F16(acc[1][3], ah[1], bh1[2], bh1[3]);
            // pass2: al x bh
            MMA_F16(acc[0][0], al[0], bh0[0], bh0[1]);
            MMA_F16(acc[0][1], al[0], bh0[2], bh0[3]);
            MMA_F16(acc[1][0], al[1], bh0[0], bh0[1]);
            MMA_F16(acc[1][1], al[1], bh0[2], bh0[3]);
            MMA_F16(acc[0][2], al[0], bh1[0], bh1[1]);
            MMA_F16(acc[0][3], al[0], bh1[2], bh1[3]);
            MMA_F16(acc[1][2], al[1], bh1[0], bh1[1]);
            MMA_F16(acc[1][3], al[1], bh1[2], bh1[3]);
        }

        if (haveW) {
            *reinterpret_cast<uint4*>(smem + 1024u + stgW + wtoff + wdoff) = pack8h(s0, s1);
        }
        const uint32_t t = stgRd;
        stgRd = stgW; stgW = stgCp; stgCp = t;
    }

    // --- epilogue: fp32 direct stores ---
    const int g = lane >> 2;
    const int tg = lane & 3;
    #pragma unroll
    for (int mb = 0; mb < 2; mb++) {
        #pragma unroll
        for (int half = 0; half < 2; half++) {
            const int r = warpM * 32 + mb * 16 + g + half * 8;
            const int s = sSlot[r];
            if (s < 0) continue;
            #pragma unroll
            for (int nb = 0; nb < 4; nb++) {
                float2 v;
                v.x = acc[mb][nb][half * 2];
                v.y = acc[mb][nb][half * 2 + 1];
                const size_t o = (size_t)s * ND + (nBase + warpN * 32 + nb * 8 + tg * 2);
                *reinterpret_cast<float2*>(out + o) = v;
            }
        }
    }
}

// ---------------------------------------------------------------------------
// Launch. Inputs (metadata order): x, w1, w2, w3, expert_indices.
// ---------------------------------------------------------------------------
extern "C" void kernel_launch(void* const* d_in, const int* in_sizes, int n_in,
                              void* d_out, int out_size) {
    const float* x  = (const float*)d_in[0];
    const float* w1 = (const float*)d_in[1];
    const float* w2 = (const float*)d_in[2];
    const float* w3 = (const float*)d_in[3];
    const int*   idx = (const int*)d_in[4];
    float* out = (float*)d_out;

    cudaFuncSetAttribute(gemm1_tc, cudaFuncAttributeMaxDynamicSharedMemorySize, SMEM1_BYTES);
    cudaFuncSetAttribute(gemm2_tc, cudaFuncAttributeMaxDynamicSharedMemorySize, SMEM2_BYTES);

    __half *xh, *xl;
    cudaGetSymbolAddress((void**)&xh, g_xh);
    cudaGetSymbolAddress((void**)&xl, g_xl);

    detect_and_zero_kernel<<<1, 256>>>(idx);
    route_kernel<<<NSLOT / 256, 256>>>(idx);

    const int nX4 = NT * ND / 4;
    split_f16_kernel<<<nX4 / 256, 256>>>(x, xh, xl, nX4);

    gemm1_tc<<<dim3(NI / BN, NSLOT / BM, NE), 512, SMEM1_BYTES>>>(w1, w3);
    gemm2_tc<<<dim3(ND / BN, NSLOT / BM, NE), 512, SMEM2_BYTES>>>(w2, out);
}

// round 11
// speedup vs baseline: 2.2918x; 1.2112x over previous
#include <cuda_runtime.h>
#include <cuda_fp16.h>
#include <cstdint>
#include <math.h>

// Problem constants
#define NT 1024
#define NA 2
#define NE 8
#define NI 2816
#define ND 1024
#define NSLOT (NT * NA)

// GEMM tiling: block 128x128x32, 512 threads (16 warps: 4M x 4N), 3-stage pipe
#define BM 128
#define BN 128
#define BK 32
#define LDS_STRIDE 80              // bytes per smem tile row (32*2 padded to 80)
#define TB (128 * LDS_STRIDE)      // one tile: 128 rows x 80B = 10240 B

// ---------------------------------------------------------------------------
// Device global scratch
// ---------------------------------------------------------------------------
__device__ int g_count[NE];
__device__ int g_slots[NE][NSLOT];
__device__ int g_is64;

__device__ __align__(16) __half g_x16[NT * ND];
__device__ __align__(16) __half g_h16[(size_t)NSLOT * NI];

// ---------------------------------------------------------------------------
// PTX helpers (base-target sm_103 features only)
// ---------------------------------------------------------------------------
__device__ __forceinline__ uint32_t smem_u32(const void* p) {
    uint32_t a;
    asm("{ .reg .u64 t; cvta.to.shared.u64 t, %1; cvt.u32.u64 %0, t; }"
        : "=r"(a) : "l"(p));
    return a;
}

#define LDSM4(R, addr) \
    asm volatile("ldmatrix.sync.aligned.m8n8.x4.shared.b16 {%0,%1,%2,%3}, [%4];" \
        : "=r"((R)[0]), "=r"((R)[1]), "=r"((R)[2]), "=r"((R)[3]) : "r"(addr))

#define MMA_F16(C, A, B0, B1) \
    asm volatile("mma.sync.aligned.m16n8k16.row.col.f32.f16.f16.f32 " \
        "{%0,%1,%2,%3}, {%4,%5,%6,%7}, {%8,%9}, {%0,%1,%2,%3};" \
        : "+f"((C)[0]), "+f"((C)[1]), "+f"((C)[2]), "+f"((C)[3]) \
        : "r"((A)[0]), "r"((A)[1]), "r"((A)[2]), "r"((A)[3]), "r"(B0), "r"(B1))

#define CP_ASYNC16(dst, src) \
    asm volatile("cp.async.cg.shared.global [%0], [%1], 16;" :: "r"(dst), "l"(src))
#define CP_COMMIT() asm volatile("cp.async.commit_group;" ::: "memory")
#define CP_WAIT(N) asm volatile("cp.async.wait_group %0;" :: "n"(N) : "memory")

__device__ __forceinline__ uint32_t pack2h(float a, float b) {
    __half2 h = __floats2half2_rn(a, b);
    return *reinterpret_cast<uint32_t*>(&h);
}
// 8 fp32 -> 8 packed fp16 (uint4)
__device__ __forceinline__ uint4 pack8h(const float4& a, const float4& b) {
    uint4 r;
    r.x = pack2h(a.x, a.y);
    r.y = pack2h(a.z, a.w);
    r.z = pack2h(b.x, b.y);
    r.w = pack2h(b.z, b.w);
    return r;
}

// ---------------------------------------------------------------------------
// Routing
// ---------------------------------------------------------------------------
__global__ void detect_and_zero_kernel(const int* __restrict__ idx32) {
    __shared__ int any;
    if (threadIdx.x == 0) any = 0;
    if (threadIdx.x < NE) g_count[threadIdx.x] = 0;
    __syncthreads();
    int local = 0;
    for (int i = threadIdx.x; i < NSLOT / 2; i += blockDim.x)
        local |= idx32[2 * i + 1];
    if (local) atomicOr(&any, 1);
    __syncthreads();
    if (threadIdx.x == 0) g_is64 = (any == 0) ? 1 : 0;
}

__global__ void route_kernel(const int* __restrict__ idx32) {
    int s = blockIdx.x * blockDim.x + threadIdx.x;
    if (s < NSLOT) {
        int e = g_is64 ? idx32[2 * s] : idx32[s];
        e &= (NE - 1);
        int p = atomicAdd(&g_count[e], 1);
        g_slots[e][p] = s;
    }
}

// ---------------------------------------------------------------------------
// x: fp32 -> fp16 (tiny)
// ---------------------------------------------------------------------------
__global__ __launch_bounds__(256) void conv_f16_kernel(
    const float* __restrict__ src, __half* __restrict__ dst, int n8)
{
    int i = blockIdx.x * blockDim.x + threadIdx.x;
    if (i >= n8) return;
    float4 a = reinterpret_cast<const float4*>(src)[2 * i];
    float4 b = reinterpret_cast<const float4*>(src)[2 * i + 1];
    reinterpret_cast<uint4*>(dst)[i] = pack8h(a, b);
}

// ---------------------------------------------------------------------------
// GEMM1: h = silu(X @ w1[e]^T) * (X @ w3[e]^T). Pure fp16 operands, fp32 acc.
// 3-stage pipeline, ONE barrier per chunk (R7 skeleton):
//   CP_WAIT -> __syncthreads -> cp.async(c+2) -> W LDG(c+1) -> MMA(c) -> W STS(c+1)
// Stage tiles: A, B1, B3 (each 128 x 32 fp16, 80B stride)
// ---------------------------------------------------------------------------
#define STAGE1B (3 * TB)                    // 30720
#define SMEM1_BYTES (1024 + 3 * STAGE1B)    // 93184

__global__ __launch_bounds__(512, 1) void gemm1_tc(
    const float* __restrict__ w1, const float* __restrict__ w3)
{
    const int e = blockIdx.z;
    const int ne = g_count[e];
    const int mBase = blockIdx.y * BM;
    if (mBase >= ne) return;
    const int nBase = blockIdx.x * BN;

    extern __shared__ char smem[];
    const uint32_t sb = smem_u32(smem);
    const int tid = threadIdx.x;
    const int wid = tid >> 5;
    const int lane = tid & 31;

    int* sSlot = reinterpret_cast<int*>(smem);
    if (tid < BM) {
        int m = mBase + tid;
        sSlot[tid] = (m < ne) ? g_slots[e][m] : -1;
    }
    __syncthreads();

    // --- A producer: one 16B granule per thread (512 granules = full tile) ---
    const int prow = tid >> 2;
    const int pcolg = tid & 3;
    const uint32_t adoff = 1024u + (uint32_t)prow * LDS_STRIDE + pcolg * 16;
    const __half* asrcp;
    {
        int s = sSlot[prow];
        int tok = (s >= 0 ? s : 0) >> 1;
        asrcp = g_x16 + (size_t)tok * ND + pcolg * 8;
    }

    // --- W producer: 16 fp32 -> 16 fp16 per thread per chunk (w1 or w3) ---
    const int wt    = tid >> 8;            // 0: w1, 1: w3
    const int wrow  = (tid & 255) >> 1;    // 0..127
    const int whalf = tid & 1;             // 16 floats each
    const float* wsrc = (wt == 0 ? w1 : w3)
        + (size_t)e * NI * ND + (size_t)(nBase + wrow) * ND + whalf * 16;
    const uint32_t wdoff = (uint32_t)wrow * LDS_STRIDE + whalf * 32;
    const uint32_t wtoff = (uint32_t)(1 + wt) * TB;   // B1 or B3 within stage

    // --- consumer: 16 warps = 4M x 4N, warp tile 32x32 ---
    const int warpM = wid & 3;
    const int warpN = wid >> 2;
    const uint32_t aoff = (uint32_t)(warpM * 32 + (lane & 15)) * LDS_STRIDE
                        + (uint32_t)(lane >> 4) * 16;
    const uint32_t boff = (uint32_t)(warpN * 32 + (lane & 7) + ((lane >> 3) & 2) * 4) * LDS_STRIDE
                        + (uint32_t)((lane >> 3) & 1) * 16;

    float acc1[2][4][4] = {};
    float acc3[2][4][4] = {};

    const int NCH = ND / BK;   // 32

    // --- prologue: cp A for chunks 0,1 (stages 0,1); convert+store W chunk 0 ---
    CP_ASYNC16(adoff + sb, asrcp);
    CP_COMMIT();
    CP_ASYNC16(adoff + sb + STAGE1B, asrcp + BK);
    CP_COMMIT();
    {
        float4 s0 = *reinterpret_cast<const float4*>(wsrc + 0);
        float4 s1 = *reinterpret_cast<const float4*>(wsrc + 4);
        float4 s2 = *reinterpret_cast<const float4*>(wsrc + 8);
        float4 s3 = *reinterpret_cast<const float4*>(wsrc + 12);
        *reinterpret_cast<uint4*>(smem + 1024u + wtoff + wdoff)      = pack8h(s0, s1);
        *reinterpret_cast<uint4*>(smem + 1024u + wtoff + wdoff + 16) = pack8h(s2, s3);
    }

    uint32_t stgRd = 0, stgW = STAGE1B, stgCp = 2 * STAGE1B;

    for (int c = 0; c < NCH; c++) {
        const bool haveCp = (c + 2 < NCH);
        const bool haveW  = (c + 1 < NCH);

        if (c + 1 < NCH) { CP_WAIT(1); } else { CP_WAIT(0); }
        __syncthreads();
        if (haveCp) {
            const int kt = (c + 2) * BK;
            CP_ASYNC16(adoff + sb + stgCp, asrcp + kt);
            CP_COMMIT();
        }
        float4 s0, s1, s2, s3;
        if (haveW) {
            const int kt = (c + 1) * BK;
            s0 = *reinterpret_cast<const float4*>(wsrc + kt + 0);
            s1 = *reinterpret_cast<const float4*>(wsrc + kt + 4);
            s2 = *reinterpret_cast<const float4*>(wsrc + kt + 8);
            s3 = *reinterpret_cast<const float4*>(wsrc + kt + 12);
        }

        const uint32_t bb = sb + 1024u + stgRd;
        const uint32_t tA = bb;
        const uint32_t tB1 = bb + TB, tB3 = bb + 2 * TB;

        #pragma unroll
        for (int kb = 0; kb < 2; kb++) {
            const uint32_t ko = kb * 32;
            uint32_t a[2][4];
            #pragma unroll
            for (int mb = 0; mb < 2; mb++)
                LDSM4(a[mb], tA + aoff + mb * (16 * LDS_STRIDE) + ko);
            #pragma unroll
            for (int nb2 = 0; nb2 < 2; nb2++) {
                const uint32_t no = nb2 * (16 * LDS_STRIDE);
                const int j0 = 2 * nb2, j1 = 2 * nb2 + 1;
                uint32_t b1[4], b3[4];
                LDSM4(b1, tB1 + boff + no + ko);
                LDSM4(b3, tB3 + boff + no + ko);
                // 8 distinct C targets
                MMA_F16(acc1[0][j0], a[0], b1[0], b1[1]);
                MMA_F16(acc1[0][j1], a[0], b1[2], b1[3]);
                MMA_F16(acc1[1][j0], a[1], b1[0], b1[1]);
                MMA_F16(acc1[1][j1], a[1], b1[2], b1[3]);
                MMA_F16(acc3[0][j0], a[0], b3[0], b3[1]);
                MMA_F16(acc3[0][j1], a[0], b3[2], b3[3]);
                MMA_F16(acc3[1][j0], a[1], b3[0], b3[1]);
                MMA_F16(acc3[1][j1], a[1], b3[2], b3[3]);
            }
        }

        if (haveW) {
            *reinterpret_cast<uint4*>(smem + 1024u + stgW + wtoff + wdoff)      = pack8h(s0, s1);
            *reinterpret_cast<uint4*>(smem + 1024u + stgW + wtoff + wdoff + 16) = pack8h(s2, s3);
        }
        const uint32_t t = stgRd;
        stgRd = stgW; stgW = stgCp; stgCp = t;
    }

    // --- epilogue: SwiGLU, store h as fp16 ---
    const int g = lane >> 2;
    const int tg = lane & 3;
    #pragma unroll
    for (int mb = 0; mb < 2; mb++) {
        #pragma unroll
        for (int half = 0; half < 2; half++) {
            const int r = warpM * 32 + mb * 16 + g + half * 8;
            const int s = sSlot[r];
            if (s < 0) continue;
            #pragma unroll
            for (int nb = 0; nb < 4; nb++) {
                const float v1a = acc1[mb][nb][half * 2];
                const float v1b = acc1[mb][nb][half * 2 + 1];
                const float v3a = acc3[mb][nb][half * 2];
                const float v3b = acc3[mb][nb][half * 2 + 1];
                const float ha = v1a / (1.0f + __expf(-v1a)) * v3a;
                const float hb = v1b / (1.0f + __expf(-v1b)) * v3b;
                const size_t o = (size_t)s * NI + (nBase + warpN * 32 + nb * 8 + tg * 2);
                *reinterpret_cast<uint32_t*>(g_h16 + o) = pack2h(ha, hb);
            }
        }
    }
}

// ---------------------------------------------------------------------------
// GEMM2: out[slot,:] = h[slot,:] @ w2[e]^T. Pure fp16 operands.
// Same 3-stage / 1-barrier scheme. Stage tiles: A, B.
// ---------------------------------------------------------------------------
#define STAGE2B (2 * TB)                    // 20480
#define SMEM2_BYTES (1024 + 3 * STAGE2B)    // 62464

__global__ __launch_bounds__(512, 1) void gemm2_tc(
    const float* __restrict__ w2, float* __restrict__ out)
{
    const int e = blockIdx.z;
    const int ne = g_count[e];
    const int mBase = blockIdx.y * BM;
    if (mBase >= ne) return;
    const int nBase = blockIdx.x * BN;

    extern __shared__ char smem[];
    const uint32_t sb = smem_u32(smem);
    const int tid = threadIdx.x;
    const int wid = tid >> 5;
    const int lane = tid & 31;

    int* sSlot = reinterpret_cast<int*>(smem);
    if (tid < BM) {
        int m = mBase + tid;
        sSlot[tid] = (m < ne) ? g_slots[e][m] : -1;
    }
    __syncthreads();

    const int prow = tid >> 2;
    const int pcolg = tid & 3;
    const uint32_t adoff = 1024u + (uint32_t)prow * LDS_STRIDE + pcolg * 16;
    const __half* asrcp;
    {
        int s = sSlot[prow];
        int sl = (s >= 0 ? s : 0);
        asrcp = g_h16 + (size_t)sl * NI + pcolg * 8;
    }

    // W producer: 8 fp32 -> 8 fp16 per thread per chunk
    const int wrow = tid >> 2;
    const int wq   = tid & 3;
    const float* wsrc = w2 + (size_t)e * ND * NI + (size_t)(nBase + wrow) * NI + wq * 8;
    const uint32_t wdoff = (uint32_t)wrow * LDS_STRIDE + wq * 16;
    const uint32_t wtoff = TB;

    const int warpM = wid & 3;
    const int warpN = wid >> 2;
    const uint32_t aoff = (uint32_t)(warpM * 32 + (lane & 15)) * LDS_STRIDE
                        + (uint32_t)(lane >> 4) * 16;
    const uint32_t boff = (uint32_t)(warpN * 32 + (lane & 7) + ((lane >> 3) & 2) * 4) * LDS_STRIDE
                        + (uint32_t)((lane >> 3) & 1) * 16;

    float acc[2][4][4] = {};

    const int NCH = NI / BK;   // 88

    // --- prologue ---
    CP_ASYNC16(adoff + sb, asrcp);
    CP_COMMIT();
    CP_ASYNC16(adoff + sb + STAGE2B, asrcp + BK);
    CP_COMMIT();
    {
        float4 s0 = *reinterpret_cast<const float4*>(wsrc + 0);
        float4 s1 = *reinterpret_cast<const float4*>(wsrc + 4);
        *reinterpret_cast<uint4*>(smem + 1024u + wtoff + wdoff) = pack8h(s0, s1);
    }

    uint32_t stgRd = 0, stgW = STAGE2B, stgCp = 2 * STAGE2B;

    for (int c = 0; c < NCH; c++) {
        const bool haveCp = (c + 2 < NCH);
        const bool haveW  = (c + 1 < NCH);

        if (c + 1 < NCH) { CP_WAIT(1); } else { CP_WAIT(0); }
        __syncthreads();
        if (haveCp) {
            const int kt = (c + 2) * BK;
            CP_ASYNC16(adoff + sb + stgCp, asrcp + kt);
            CP_COMMIT();
        }
        float4 s0, s1;
        if (haveW) {
            const int kt = (c + 1) * BK;
            s0 = *reinterpret_cast<const float4*>(wsrc + kt + 0);
            s1 = *reinterpret_cast<const float4*>(wsrc + kt + 4);
        }

        const uint32_t bb = sb + 1024u + stgRd;
        const uint32_t tA = bb;
        const uint32_t tBh = bb + TB;

        #pragma unroll
        for (int kb = 0; kb < 2; kb++) {
            const uint32_t ko = kb * 32;
            uint32_t a[2][4];
            #pragma unroll
            for (int mb = 0; mb < 2; mb++)
                LDSM4(a[mb], tA + aoff + mb * (16 * LDS_STRIDE) + ko);
            uint32_t bh0[4], bh1[4];
            LDSM4(bh0, tBh + boff + ko);
            LDSM4(bh1, tBh + boff + 16 * LDS_STRIDE + ko);
            MMA_F16(acc[0][0], a[0], bh0[0], bh0[1]);
            MMA_F16(acc[0][1], a[0], bh0[2], bh0[3]);
            MMA_F16(acc[1][0], a[1], bh0[0], bh0[1]);
            MMA_F16(acc[1][1], a[1], bh0[2], bh0[3]);
            MMA_F16(acc[0][2], a[0], bh1[0], bh1[1]);
            MMA_F16(acc[0][3], a[0], bh1[2], bh1[3]);
            MMA_F16(acc[1][2], a[1], bh1[0], bh1[1]);
            MMA_F16(acc[1][3], a[1], bh1[2], bh1[3]);
        }

        if (haveW) {
            *reinterpret_cast<uint4*>(smem + 1024u + stgW + wtoff + wdoff) = pack8h(s0, s1);
        }
        const uint32_t t = stgRd;
        stgRd = stgW; stgW = stgCp; stgCp = t;
    }

    // --- epilogue: fp32 direct stores ---
    const int g = lane >> 2;
    const int tg = lane & 3;
    #pragma unroll
    for (int mb = 0; mb < 2; mb++) {
        #pragma unroll
        for (int half = 0; half < 2; half++) {
            const int r = warpM * 32 + mb * 16 + g + half * 8;
            const int s = sSlot[r];
            if (s < 0) continue;
            #pragma unroll
            for (int nb = 0; nb < 4; nb++) {
                float2 v;
                v.x = acc[mb][nb][half * 2];
                v.y = acc[mb][nb][half * 2 + 1];
                const size_t o = (size_t)s * ND + (nBase + warpN * 32 + nb * 8 + tg * 2);
                *reinterpret_cast<float2*>(out + o) = v;
            }
        }
    }
}

// ---------------------------------------------------------------------------
// Launch. Inputs (metadata order): x, w1, w2, w3, expert_indices.
// ---------------------------------------------------------------------------
extern "C" void kernel_launch(void* const* d_in, const int* in_sizes, int n_in,
                              void* d_out, int out_size) {
    const float* x  = (const float*)d_in[0];
    const float* w1 = (const float*)d_in[1];
    const float* w2 = (const float*)d_in[2];
    const float* w3 = (const float*)d_in[3];
    const int*   idx = (const int*)d_in[4];
    float* out = (float*)d_out;

    cudaFuncSetAttribute(gemm1_tc, cudaFuncAttributeMaxDynamicSharedMemorySize, SMEM1_BYTES);
    cudaFuncSetAttribute(gemm2_tc, cudaFuncAttributeMaxDynamicSharedMemorySize, SMEM2_BYTES);

    __half* x16;
    cudaGetSymbolAddress((void**)&x16, g_x16);

    detect_and_zero_kernel<<<1, 256>>>(idx);
    route_kernel<<<NSLOT / 256, 256>>>(idx);

    const int nX8 = NT * ND / 8;
    conv_f16_kernel<<<nX8 / 256, 256>>>(x, x16, nX8);

    gemm1_tc<<<dim3(NI / BN, NSLOT / BM, NE), 512, SMEM1_BYTES>>>(w1, w3);
    gemm2_tc<<<dim3(ND / BN, NSLOT / BM, NE), 512, SMEM2_BYTES>>>(w2, out);
}